// round 14
// baseline (speedup 1.0000x reference)
#include <cuda_runtime.h>
#include <cuda_bf16.h>
#include <cstdint>

#define B_ 128
#define L_ 1024
#define H_ 256
#define E_ 128
#define V_ 50000
#define X_ 100
#define VX_ 50100
#define NTILE 391
#define LGRID 296

// d_out float offsets (tuple order: final_dist, h, c, c_t, a, p_gen, coverage_next)
#define O_FD  0
#define O_H   6412800
#define O_C   6445568
#define O_CT  6478336
#define O_A   6543872
#define O_PG  6674944
#define O_COV 6675072

// ---------------- static device scratch (no allocations) ----------------
__device__ __align__(256) float g_prepT[640 * B_];
__device__ __align__(256) float g_h0T[256 * B_];
__device__ __align__(256) float g_xT[E_ * B_];
__device__ __align__(256) float g_gatesT[4 * H_ * B_];
__device__ __align__(256) float g_hcT[2 * H_ * B_];
__device__ __align__(256) float g_decT[2 * H_ * B_];
__device__ __align__(256) float g_ctT[2 * H_ * B_];       // c_t accumulated by k_ctx
__device__ __align__(256) float g_hidT[H_ * B_];          // [k][b]
__device__ __align__(256) float g_energy[B_ * L_];
__device__ __align__(256) float g_logits[B_ * V_];        // holds exp(logit+bias)
__device__ __align__(256) float g_tsum[B_ * NTILE];
__device__ __align__(256) float g_S[B_];                  // per-row scale p_gen/S
__device__ int g_done;
__device__ int g_flag;

// ---------------- helpers ----------------
__device__ __forceinline__ float fsig(float x) {
    return __fdividef(1.0f, 1.0f + __expf(-x));
}
__device__ __forceinline__ float ftanh(float x) {
    float e = __expf(2.0f * x);
    return 1.0f - __fdividef(2.0f, 1.0f + e);
}
// hardware tanh (MUFU.TANH) — used only on the attention-energy path
__device__ __forceinline__ float ftanha(float x) {
    float r;
    asm("tanh.approx.f32 %0, %1;" : "=f"(r) : "f"(x));
    return r;
}
__device__ __forceinline__ uint32_t pkbf2(float a, float b) {
    uint32_t r;
    asm("cvt.rn.bf16x2.f32 %0, %2, %1;" : "=r"(r) : "f"(a), "f"(b));
    return r;
}
// PDL primitives
__device__ __forceinline__ void gdep_wait() {
    asm volatile("griddepcontrol.wait;" ::: "memory");
}
__device__ __forceinline__ void gdep_launch() {
    asm volatile("griddepcontrol.launch_dependents;");
}

// =============== K0: zero scratch + prep transposed activations (fused) ===============
__global__ void k_prep_zero(const int* __restrict__ y_t, const float* __restrict__ c_t_1,
                            const float* __restrict__ embed_W, const float* __restrict__ h0) {
    gdep_launch();
    int bid = blockIdx.x, t = threadIdx.x;     // grid 512 x 256
    int i = bid * 256 + t;
    if (i == 0) { g_done = 0; g_flag = 0; }
    if (i < E_ * B_)      g_xT[i] = 0.0f;
    if (i < 4 * H_ * B_)  g_gatesT[i] = 0.0f;
    if (i < 2 * H_ * B_)  { g_decT[i] = 0.0f; g_ctT[i] = 0.0f; }
    if (i < H_ * B_)      g_hidT[i] = 0.0f;
    if (bid < B_) {
        int b = bid;
        for (int k = t; k < 512; k += 256) g_prepT[k * 128 + b] = c_t_1[b * 512 + k];
        int y = y_t[b];
        if (t < 128) g_prepT[(512 + t) * 128 + b] = embed_W[y * 128 + t];
        g_h0T[t * 128 + b] = h0[b * 256 + t];
    }
}

// =============== unified small GEMM (1 chunk of 64 k per block) ===============
__global__ void __launch_bounds__(256) k_gemm(
    const float* __restrict__ actA, const float* __restrict__ WA, int sWA, int KA,
    const float* __restrict__ actB, const float* __restrict__ WB, int sWB,
    const float* __restrict__ bias1, const float* __restrict__ bias2,
    float* __restrict__ outT)
{
    __shared__ float s_act[32][65];
    __shared__ float s_w[32][64];
    int tid = threadIdx.x;
    int lane = tid & 31, wp = tid >> 5;
    int j0 = blockIdx.x * 32;
    int b  = blockIdx.y * 32 + lane;
    int k0 = blockIdx.z * 64;

    const float* asrc; const float* wsrc; int ws; int kr;
    if (k0 < KA) { asrc = actA; wsrc = WA; ws = sWA; kr = k0; }
    else         { asrc = actB; wsrc = WB; ws = sWB; kr = k0 - KA; }
    // stage W pre-wait (inputs; overlaps predecessor tail)
    {
        int idx = tid * 2;
        int j = idx >> 4, f = (idx & 15) * 4;
        float4 v = *(const float4*)&wsrc[(j0 + j) * ws + kr + f];
        *(float4*)&s_w[j][f] = v;
        idx++;
        j = idx >> 4; f = (idx & 15) * 4;
        v = *(const float4*)&wsrc[(j0 + j) * ws + kr + f];
        *(float4*)&s_w[j][f] = v;
    }
    gdep_wait();
    gdep_launch();
#pragma unroll
    for (int r = 0; r < 8; r++) {
        int k = r * 8 + wp;
        s_act[lane][k] = asrc[(kr + k) * 128 + b];
    }
    __syncthreads();
    float acc0 = 0.0f, acc1 = 0.0f, acc2 = 0.0f, acc3 = 0.0f;
#pragma unroll
    for (int kk = 0; kk < 64; kk += 4) {
        float a0 = s_act[lane][kk + 0];
        float a1 = s_act[lane][kk + 1];
        float a2 = s_act[lane][kk + 2];
        float a3 = s_act[lane][kk + 3];
        float4 w0 = *(const float4*)&s_w[wp * 4 + 0][kk];
        float4 w1 = *(const float4*)&s_w[wp * 4 + 1][kk];
        float4 w2 = *(const float4*)&s_w[wp * 4 + 2][kk];
        float4 w3 = *(const float4*)&s_w[wp * 4 + 3][kk];
        acc0 += w0.x * a0 + w0.y * a1 + w0.z * a2 + w0.w * a3;
        acc1 += w1.x * a0 + w1.y * a1 + w1.z * a2 + w1.w * a3;
        acc2 += w2.x * a0 + w2.y * a1 + w2.z * a2 + w2.w * a3;
        acc3 += w3.x * a0 + w3.y * a1 + w3.z * a2 + w3.w * a3;
    }
    int j = j0 + wp * 4;
    if (blockIdx.z == 0 && bias1) {
        acc0 += bias1[j + 0]; acc1 += bias1[j + 1]; acc2 += bias1[j + 2]; acc3 += bias1[j + 3];
        if (bias2) {
            acc0 += bias2[j + 0]; acc1 += bias2[j + 1]; acc2 += bias2[j + 2]; acc3 += bias2[j + 3];
        }
    }
    atomicAdd(&outT[(j + 0) * 128 + b], acc0);
    atomicAdd(&outT[(j + 1) * 128 + b], acc1);
    atomicAdd(&outT[(j + 2) * 128 + b], acc2);
    atomicAdd(&outT[(j + 3) * 128 + b], acc3);
}

// =============== K3: LSTM pointwise (wide grid) ===============
__global__ void k_lstm(const float* __restrict__ c0, float* __restrict__ outp) {
    gdep_wait();
    gdep_launch();
    int i = blockIdx.x * 64 + threadIdx.x;
    int t = i >> 7, b = i & 127;
    float gi = g_gatesT[i];
    float gf = g_gatesT[i + 32768];
    float gg = g_gatesT[i + 65536];
    float go = g_gatesT[i + 98304];
    float c0v = c0[b * 256 + t];
    float cc = fsig(gf) * c0v + fsig(gi) * ftanh(gg);
    float hh = fsig(go) * ftanh(cc);
    outp[O_H + b * 256 + t] = hh;
    outp[O_C + b * 256 + t] = cc;
    g_hcT[t * 128 + b] = hh;
    g_hcT[(256 + t) * 128 + b] = cc;
}

// =============== K5: attention energy (streams enc_feats, __ldcs + MUFU.TANH) ===============
__global__ void k_energy(const float* __restrict__ enc_feats,
                         const float* __restrict__ coverage,
                         const float* __restrict__ Wc_W, const float* __restrict__ v_W) {
    int idx0 = blockIdx.x * 8;
    int b = idx0 >> 10;
    __shared__ float sdec[512], swc[512], sv[512];
    int tid = threadIdx.x;
    for (int i = tid; i < 512; i += 256) {
        swc[i]  = Wc_W[i];
        sv[i]   = v_W[i];
    }
    gdep_wait();
    gdep_launch();
    for (int i = tid; i < 512; i += 256) sdec[i] = g_decT[i * 128 + b];
    __syncthreads();
    int w = tid >> 5, lane = tid & 31;
    int idx = idx0 + w;
    float cov = coverage[idx];
    const float* base = enc_feats + (size_t)idx * 512;
    float e = 0.0f;
#pragma unroll
    for (int c = 0; c < 4; c++) {
        int d0 = c * 128 + lane * 4;
        float4 f  = __ldcs((const float4*)(base + d0));
        float4 dv = *(const float4*)(sdec + d0);
        float4 wv = *(const float4*)(swc + d0);
        float4 vv = *(const float4*)(sv + d0);
        e += ftanha(f.x + dv.x + cov * wv.x) * vv.x;
        e += ftanha(f.y + dv.y + cov * wv.y) * vv.y;
        e += ftanha(f.z + dv.z + cov * wv.z) * vv.z;
        e += ftanha(f.w + dv.w + cov * wv.w) * vv.w;
    }
#pragma unroll
    for (int o = 16; o; o >>= 1) e += __shfl_xor_sync(0xffffffffu, e, o);
    if (lane == 0) g_energy[idx] = e;
}

// =============== K6: softmax over L ===============
__global__ void k_softmax_a(const float* __restrict__ mask, const float* __restrict__ coverage,
                            float* __restrict__ outp) {
    gdep_wait();
    gdep_launch();
    int b = blockIdx.x, tid = threadIdx.x;
    __shared__ float red[256];
    float e[4];
#pragma unroll
    for (int j = 0; j < 4; j++) e[j] = g_energy[b * 1024 + tid + j * 256];
    float m = fmaxf(fmaxf(e[0], e[1]), fmaxf(e[2], e[3]));
    red[tid] = m; __syncthreads();
    for (int s = 128; s > 0; s >>= 1) { if (tid < s) red[tid] = fmaxf(red[tid], red[tid + s]); __syncthreads(); }
    float M = red[0]; __syncthreads();
    float ev[4], sum = 0.0f;
#pragma unroll
    for (int j = 0; j < 4; j++) {
        ev[j] = __expf(e[j] - M) * mask[b * 1024 + tid + j * 256];
        sum += ev[j];
    }
    red[tid] = sum; __syncthreads();
    for (int s = 128; s > 0; s >>= 1) { if (tid < s) red[tid] += red[tid + s]; __syncthreads(); }
    float inv = __fdividef(1.0f, red[0]);
#pragma unroll
    for (int j = 0; j < 4; j++) {
        int i = b * 1024 + tid + j * 256;
        float a = ev[j] * inv;
        outp[O_A + i] = a;
        outp[O_COV + i] = coverage[i] + a;
    }
}

// =============== K7: c_t partials (streams enc_outs, __ldcs) — accumulates c_t ===============
__global__ void k_ctx(const float* __restrict__ enc_outs, const float* __restrict__ outp) {
    gdep_wait();
    gdep_launch();
    int chunk = blockIdx.x, b = blockIdx.y;
    __shared__ float sa[64];
    int tid = threadIdx.x;
    if (tid < 64) sa[tid] = outp[O_A + b * 1024 + chunk * 64 + tid];
    __syncthreads();
    const float2* p = (const float2*)(enc_outs + ((size_t)b * 1024 + chunk * 64) * 512);
    float2 acc = make_float2(0.0f, 0.0f);
#pragma unroll 8
    for (int i = 0; i < 64; i++) {
        float2 v = __ldcs(p + i * 256 + tid);
        float a = sa[i];
        acc.x += a * v.x;
        acc.y += a * v.y;
    }
    atomicAdd(&g_ctT[(2 * tid) * 128 + b], acc.x);
    atomicAdd(&g_ctT[(2 * tid + 1) * 128 + b], acc.y);
}

// =============== K8: c_t copy-out + p_gen (runs OFF critical path on s2) ===============
__global__ void k_finalize(const float* __restrict__ pgen_W, const float* __restrict__ pgen_b,
                           float* __restrict__ outp) {
    gdep_wait();
    gdep_launch();
    int b = blockIdx.x, tid = threadIdx.x;     // 512
    __shared__ float red[512];
    float ct = g_ctT[tid * 128 + b];
    outp[O_CT + b * 512 + tid] = ct;
    float p = pgen_W[tid] * ct;
    float z2 = (tid < 256) ? outp[O_H + b * 256 + tid] : outp[O_C + b * 256 + (tid - 256)];
    p += pgen_W[512 + tid] * z2;
    if (tid < 128) p += pgen_W[1024 + tid] * g_xT[tid * 128 + b];
    red[tid] = p; __syncthreads();
    for (int st = 256; st > 0; st >>= 1) { if (tid < st) red[tid] += red[tid + st]; __syncthreads(); }
    if (tid == 0) outp[O_PG + b] = fsig(red[0] + pgen_b[0]);
}

// =============== K10: logits GEMM + IN-KERNEL softmax normalize (one-wave grid barrier) ===============
// LGRID=296 = 2 blocks/SM x 148: all blocks co-resident (91KB smem -> exactly 2/SM),
// so a spin barrier is safe. The only concurrent grid (k_finalize) terminates
// independently. After the barrier, block 0 publishes scale = p_gen/S per row;
// every block normalizes its own (L2-hot) exp tiles straight into final_dist.
#define SA_STRIDE 132
#define SB_STRIDE 20
#define SB_WORDS  (128 * SB_STRIDE)
#define SMEM_LOGITS ((128 * SA_STRIDE + 2 * SB_WORDS) * 4 + 128 * 4 + 128 * 4 * 4)

__global__ void __launch_bounds__(256) k_logits_mma(const float* __restrict__ outW,
                                                    const float* __restrict__ outb,
                                                    const float* __restrict__ extra_zeros,
                                                    float* __restrict__ outp) {
    extern __shared__ uint32_t smem_dyn[];
    uint32_t* sA = smem_dyn;
    uint32_t* sB = sA + 128 * SA_STRIDE;
    float* s_bias = (float*)(sB + 2 * SB_WORDS);
    float* s_red  = s_bias + 128;                 // [128][4]

    int tid = threadIdx.x;
    int lane = tid & 31, wid = tid >> 5;
    int wm = wid >> 2, wn = wid & 3;
    int g = lane >> 2, tg = lane & 3;

    const int tile0 = blockIdx.x;

    // ---- pre-wait: inputs only (first tile's bias + first B chunk) ----
    {
        int v00 = tile0 * 128;
        if (tid < 128) s_bias[tid] = (v00 + tid < V_) ? outb[v00 + tid] : 0.0f;
    }
    float4 pw[4];
#pragma unroll
    for (int r = 0; r < 4; r++) {
        int idx = r * 256 + tid;
        int v = tile0 * 128 + (idx >> 3), f = idx & 7;
        pw[r] = (v < V_) ? __ldcs((const float4*)&outW[(size_t)v * 256 + f * 4])
                         : make_float4(0.f, 0.f, 0.f, 0.f);
    }
    gdep_wait();
    // ---- stage A once (tile-independent) ----
#pragma unroll 8
    for (int r = 0; r < 64; r++) {
        int idx = r * 256 + tid;
        int b = idx & 127, w = idx >> 7;
        float lo = g_hidT[(2 * w) * 128 + b];
        float hi = g_hidT[(2 * w + 1) * 128 + b];
        sA[b * SA_STRIDE + w] = pkbf2(lo, hi);
    }

    for (int tile = tile0; tile < NTILE; tile += LGRID) {
        const int v0 = tile * 128;
        if (tile != tile0) {
            __syncthreads();
            if (tid < 128) s_bias[tid] = (v0 + tid < V_) ? outb[v0 + tid] : 0.0f;
#pragma unroll
            for (int r = 0; r < 4; r++) {
                int idx = r * 256 + tid;
                int v = v0 + (idx >> 3), f = idx & 7;
                pw[r] = (v < V_) ? __ldcs((const float4*)&outW[(size_t)v * 256 + f * 4])
                                 : make_float4(0.f, 0.f, 0.f, 0.f);
            }
        }
#pragma unroll
        for (int r = 0; r < 4; r++) {
            int idx = r * 256 + tid;
            int v = idx >> 3, f = idx & 7;
            sB[v * SB_STRIDE + f * 2]     = pkbf2(pw[r].x, pw[r].y);
            sB[v * SB_STRIDE + f * 2 + 1] = pkbf2(pw[r].z, pw[r].w);
        }
        __syncthreads();

        float acc[4][4][4];
#pragma unroll
        for (int mt = 0; mt < 4; mt++)
#pragma unroll
            for (int nt = 0; nt < 4; nt++)
#pragma unroll
                for (int q = 0; q < 4; q++) acc[mt][nt][q] = 0.0f;

#pragma unroll 1
        for (int it = 0; it < 8; it++) {
            if (it < 7) {
                int k0n = (it + 1) * 32;
#pragma unroll
                for (int r = 0; r < 4; r++) {
                    int idx = r * 256 + tid;
                    int v = v0 + (idx >> 3), f = idx & 7;
                    pw[r] = (v < V_) ? __ldcs((const float4*)&outW[(size_t)v * 256 + k0n + f * 4])
                                     : make_float4(0.f, 0.f, 0.f, 0.f);
                }
            }
            const uint32_t* sBp = sB + (it & 1) * SB_WORDS;
            int aw = it * 16;
#pragma unroll
            for (int kk = 0; kk < 2; kk++) {
                int kw = kk * 8 + tg;
                uint32_t a[4][4];
#pragma unroll
                for (int mt = 0; mt < 4; mt++) {
                    int r0 = wm * 64 + mt * 16 + g;
                    a[mt][0] = sA[r0 * SA_STRIDE + aw + kw];
                    a[mt][1] = sA[(r0 + 8) * SA_STRIDE + aw + kw];
                    a[mt][2] = sA[r0 * SA_STRIDE + aw + kw + 4];
                    a[mt][3] = sA[(r0 + 8) * SA_STRIDE + aw + kw + 4];
                }
#pragma unroll
                for (int nt = 0; nt < 4; nt++) {
                    int n0 = wn * 32 + nt * 8 + g;
                    uint32_t b0 = sBp[n0 * SB_STRIDE + kw];
                    uint32_t b1 = sBp[n0 * SB_STRIDE + kw + 4];
#pragma unroll
                    for (int mt = 0; mt < 4; mt++) {
                        asm volatile(
                            "mma.sync.aligned.m16n8k16.row.col.f32.bf16.bf16.f32 "
                            "{%0,%1,%2,%3},{%4,%5,%6,%7},{%8,%9},{%0,%1,%2,%3};"
                            : "+f"(acc[mt][nt][0]), "+f"(acc[mt][nt][1]),
                              "+f"(acc[mt][nt][2]), "+f"(acc[mt][nt][3])
                            : "r"(a[mt][0]), "r"(a[mt][1]), "r"(a[mt][2]), "r"(a[mt][3]),
                              "r"(b0), "r"(b1));
                    }
                }
            }
            if (it < 7) {
                uint32_t* sBn = sB + ((it + 1) & 1) * SB_WORDS;
#pragma unroll
                for (int r = 0; r < 4; r++) {
                    int idx = r * 256 + tid;
                    int v = idx >> 3, f = idx & 7;
                    sBn[v * SB_STRIDE + f * 2]     = pkbf2(pw[r].x, pw[r].y);
                    sBn[v * SB_STRIDE + f * 2 + 1] = pkbf2(pw[r].z, pw[r].w);
                }
            }
            __syncthreads();
        }

        // ---- epilogue: exp(logit+bias) stored; per-row tile sums ----
        int cbase = wn * 32 + tg * 2;
        bool val[4];
#pragma unroll
        for (int nt = 0; nt < 4; nt++) val[nt] = (v0 + cbase + nt * 8) < V_;
#pragma unroll
        for (int mt = 0; mt < 4; mt++) {
#pragma unroll
            for (int h = 0; h < 2; h++) {
                int row = wm * 64 + mt * 16 + g + h * 8;
                float s = 0.0f;
#pragma unroll
                for (int nt = 0; nt < 4; nt++) {
                    if (val[nt]) {
                        float bv0 = s_bias[cbase + nt * 8];
                        float bv1 = s_bias[cbase + nt * 8 + 1];
                        float e0 = __expf(acc[mt][nt][2 * h]     + bv0);
                        float e1 = __expf(acc[mt][nt][2 * h + 1] + bv1);
                        *(float2*)&g_logits[(size_t)row * V_ + v0 + cbase + nt * 8] = make_float2(e0, e1);
                        s += e0 + e1;
                    }
                }
                s += __shfl_xor_sync(0xffffffffu, s, 1);
                s += __shfl_xor_sync(0xffffffffu, s, 2);
                if (tg == 0) s_red[row * 4 + wn] = s;
            }
        }
        __syncthreads();
        if (tid < 128) {
            float s = s_red[tid * 4 + 0] + s_red[tid * 4 + 1] + s_red[tid * 4 + 2] + s_red[tid * 4 + 3];
            g_tsum[tid * NTILE + tile] = s;
        }
    }

    // ---- one-wave grid barrier + scale publication ----
    __threadfence();
    __syncthreads();
    if (tid == 0) atomicAdd(&g_done, 1);
    if (blockIdx.x == 0) {
        if (tid == 0) { while (atomicAdd(&g_done, 0) < LGRID) { } }
        __syncthreads();
        if (tid < 128) {
            float S = 0.0f;
#pragma unroll 4
            for (int i = 0; i < NTILE; i++) S += __ldcg(&g_tsum[tid * NTILE + i]);
            g_S[tid] = __fdividef(__ldcg(&outp[O_PG + tid]), S);
        }
        __threadfence();
        __syncthreads();
        if (tid == 0) atomicExch(&g_flag, 1);
    } else {
        if (tid == 0) { while (atomicAdd(&g_flag, 0) == 0) { } }
        __syncthreads();
        __threadfence();
    }
    gdep_launch();

    // ---- normalize own tiles (L2-hot) straight into final_dist ----
    if (tid < 128) s_bias[tid] = __ldcg(&g_S[tid]);     // reuse s_bias for scales
    __syncthreads();
    for (int tile = tile0; tile < NTILE; tile += LGRID) {
        const int v0 = tile * 128;
#pragma unroll
        for (int r = 0; r < 16; r++) {
            int idx = r * 256 + tid;
            int row = idx >> 5, q = idx & 31;
            int v = v0 + q * 4;
            if (v < V_) {
                float4 lg = *(const float4*)&g_logits[(size_t)row * V_ + v];
                float sc = s_bias[row];
                float4 o = make_float4(sc * lg.x, sc * lg.y, sc * lg.z, sc * lg.w);
                *(float4*)&outp[O_FD + (size_t)row * VX_ + v] = o;
            }
        }
    }
    // extra-zeros region (v in [V, V+X)), 50 blocks x 256 = 12800 = 128*100
    if (tile0 < 50) {
        int idx = tile0 * 256 + tid;
        int b = idx / 100, v = idx % 100;
        outp[O_FD + (size_t)b * VX_ + V_ + v] = extra_zeros[b * X_ + v];
    }
}

// =============== K13: pointer scatter-add ===============
__global__ void k_scatter(const int* __restrict__ ext_vocab, float* __restrict__ outp) {
    gdep_wait();
    gdep_launch();
    int i = blockIdx.x * 256 + threadIdx.x;
    int b = i >> 10;
    float pg = outp[O_PG + b];
    float av = outp[O_A + i];
    atomicAdd(&outp[O_FD + b * VX_ + ext_vocab[i]], (1.0f - pg) * av);
}

// ---------------- PDL launch helper (main stream) ----------------
template <typename... Args>
static inline void pdl_launch(dim3 g, dim3 b, size_t shm,
                              void (*f)(Args...), Args... a) {
    cudaLaunchConfig_t cfg = {};
    cfg.gridDim = g; cfg.blockDim = b; cfg.dynamicSmemBytes = shm; cfg.stream = 0;
    cudaLaunchAttribute at[1];
    at[0].id = cudaLaunchAttributeProgrammaticStreamSerialization;
    at[0].val.programmaticStreamSerializationAllowed = 1;
    cfg.attrs = at; cfg.numAttrs = 1;
    cudaLaunchKernelEx(&cfg, f, a...);
}

// ======================================================================
extern "C" void kernel_launch(void* const* d_in, const int* in_sizes, int n_in,
                              void* d_out, int out_size) {
    (void)in_sizes; (void)n_in; (void)out_size;
    const int*   y_t       = (const int*)d_in[0];
    const float* h0        = (const float*)d_in[1];
    const float* c0        = (const float*)d_in[2];
    const float* enc_outs  = (const float*)d_in[3];
    const float* enc_feats = (const float*)d_in[4];
    const float* mask      = (const float*)d_in[5];
    const float* c_t_1     = (const float*)d_in[6];
    const float* extra_z   = (const float*)d_in[7];
    const int*   ext_vocab = (const int*)d_in[8];
    const float* coverage  = (const float*)d_in[9];
    const float* embed_W   = (const float*)d_in[10];
    const float* Wih       = (const float*)d_in[11];
    const float* Whh       = (const float*)d_in[12];
    const float* bih       = (const float*)d_in[13];
    const float* bhh       = (const float*)d_in[14];
    const float* xctx_W    = (const float*)d_in[15];
    const float* xctx_b    = (const float*)d_in[16];
    const float* Ws_W      = (const float*)d_in[17];
    const float* Ws_b      = (const float*)d_in[18];
    const float* Wc_W      = (const float*)d_in[19];
    const float* v_W       = (const float*)d_in[20];
    const float* pgen_W    = (const float*)d_in[21];
    const float* pgen_b    = (const float*)d_in[22];
    const float* proj_W    = (const float*)d_in[23];
    const float* proj_b    = (const float*)d_in[24];
    const float* out_W     = (const float*)d_in[25];
    const float* out_b     = (const float*)d_in[26];
    float* outp = (float*)d_out;

    float* d_xT;     cudaGetSymbolAddress((void**)&d_xT, g_xT);
    float* d_gatesT; cudaGetSymbolAddress((void**)&d_gatesT, g_gatesT);
    float* d_hcT;    cudaGetSymbolAddress((void**)&d_hcT, g_hcT);
    float* d_decT;   cudaGetSymbolAddress((void**)&d_decT, g_decT);
    float* d_ctT;    cudaGetSymbolAddress((void**)&d_ctT, g_ctT);
    float* d_hidT;   cudaGetSymbolAddress((void**)&d_hidT, g_hidT);
    float* d_prepT;  cudaGetSymbolAddress((void**)&d_prepT, g_prepT);
    float* d_h0T;    cudaGetSymbolAddress((void**)&d_h0T, g_h0T);
    const float* cnull = nullptr;

    cudaFuncSetAttribute(k_logits_mma, cudaFuncAttributeMaxDynamicSharedMemorySize, SMEM_LOGITS);

    // side stream + events for fork-join capture (host handles only; no device mem)
    cudaStream_t s2;
    cudaStreamCreateWithFlags(&s2, cudaStreamNonBlocking);
    cudaEvent_t ev0, evG, ev1, ev2, evC, evF;
    cudaEventCreateWithFlags(&ev0, cudaEventDisableTiming);
    cudaEventCreateWithFlags(&evG, cudaEventDisableTiming);
    cudaEventCreateWithFlags(&ev1, cudaEventDisableTiming);
    cudaEventCreateWithFlags(&ev2, cudaEventDisableTiming);
    cudaEventCreateWithFlags(&evC, cudaEventDisableTiming);
    cudaEventCreateWithFlags(&evF, cudaEventDisableTiming);

    k_prep_zero<<<512, 256>>>(y_t, c_t_1, embed_W, h0);

    // fork: gates h0-half (K=256, biases) on s2, overlapping the x GEMM on main
    cudaEventRecord(ev0, 0);
    cudaStreamWaitEvent(s2, ev0, 0);
    k_gemm<<<dim3(32, 4, 4), 256, 0, s2>>>(d_h0T, Whh, 256, 256,
                                           cnull, cnull, 0, bih, bhh, d_gatesT);
    cudaEventRecord(evG, s2);

    // x = [c_t_1, emb] @ xctx_W.T + xctx_b   (K=640 -> 10 chunks)
    pdl_launch(dim3(4, 4, 10), dim3(256), 0, k_gemm,
               (const float*)d_prepT, xctx_W, 640, 640,
               cnull, cnull, 0, xctx_b, cnull, (float*)d_xT);
    // gates x-half (K=128 -> 2 chunks, no bias — applied in h0-half)
    pdl_launch(dim3(32, 4, 2), dim3(256), 0, k_gemm,
               (const float*)d_xT, Wih, 128, 128,
               cnull, cnull, 0, cnull, cnull, (float*)d_gatesT);
    // join both gates halves before lstm
    cudaStreamWaitEvent(0, evG, 0);
    pdl_launch(dim3(512), dim3(64), 0, k_lstm, c0, outp);

    // fork: h-half of hid GEMM overlaps the attention phase
    cudaEventRecord(ev1, 0);
    cudaStreamWaitEvent(s2, ev1, 0);
    k_gemm<<<dim3(8, 4, 4), 256, 0, s2>>>(d_hcT, proj_W, 768, 256,
                                          cnull, cnull, 0, proj_b, cnull, d_hidT);
    cudaEventRecord(ev2, s2);

    // dec = [h,c]@Ws_W.T + Ws_b              (K=512 -> 8 chunks)
    pdl_launch(dim3(16, 4, 8), dim3(256), 0, k_gemm,
               (const float*)d_hcT, Ws_W, 512, 512,
               cnull, cnull, 0, Ws_b, cnull, (float*)d_decT);
    pdl_launch(dim3(B_ * L_ / 8), dim3(256), 0, k_energy,
               enc_feats, coverage, Wc_W, v_W);
    pdl_launch(dim3(B_), dim3(256), 0, k_softmax_a, mask, coverage, outp);
    pdl_launch(dim3(16, B_), dim3(256), 0, k_ctx, enc_outs, (const float*)outp);

    // fork: finalize (c_t copy-out + p_gen) on s2 — completes during hid-ct GEMM
    cudaEventRecord(evC, 0);
    cudaStreamWaitEvent(s2, evC, 0);
    k_finalize<<<B_, 512, 0, s2>>>(pgen_W, pgen_b, outp);
    cudaEventRecord(evF, s2);

    // ct-half of hid GEMM (K=512 -> 8 chunks), no bias (added in h-half)
    pdl_launch(dim3(8, 4, 8), dim3(256), 0, k_gemm,
               (const float*)d_ctT, (const float*)(proj_W + 256), 768, 512,
               cnull, cnull, 0, cnull, cnull, (float*)d_hidT);
    // joins: logits needs both hid halves AND p_gen (for in-kernel normalize)
    cudaStreamWaitEvent(0, ev2, 0);
    cudaStreamWaitEvent(0, evF, 0);
    pdl_launch(dim3(LGRID), dim3(256), (size_t)SMEM_LOGITS, k_logits_mma,
               out_W, out_b, extra_z, outp);
    pdl_launch(dim3(B_ * L_ / 256), dim3(256), 0, k_scatter, ext_vocab, outp);
}

// round 15
// speedup vs baseline: 1.2313x; 1.2313x over previous
#include <cuda_runtime.h>
#include <cuda_bf16.h>
#include <cstdint>

#define B_ 128
#define L_ 1024
#define H_ 256
#define E_ 128
#define V_ 50000
#define X_ 100
#define VX_ 50100
#define NTILE 391
#define LGRID 296

// d_out float offsets (tuple order: final_dist, h, c, c_t, a, p_gen, coverage_next)
#define O_FD  0
#define O_H   6412800
#define O_C   6445568
#define O_CT  6478336
#define O_A   6543872
#define O_PG  6674944
#define O_COV 6675072

// ---------------- static device scratch (no allocations) ----------------
__device__ __align__(256) float g_prepT[640 * B_];
__device__ __align__(256) float g_h0T[256 * B_];
__device__ __align__(256) float g_xT[E_ * B_];
__device__ __align__(256) float g_gatesT[4 * H_ * B_];
__device__ __align__(256) float g_hcT[2 * H_ * B_];
__device__ __align__(256) float g_decT[2 * H_ * B_];
__device__ __align__(256) float g_ctT[2 * H_ * B_];       // c_t accumulated by k_ctx
__device__ __align__(256) float g_hidT[H_ * B_];          // [k][b]
__device__ __align__(256) float g_energy[B_ * L_];
__device__ __align__(256) float g_logits[B_ * V_];        // holds exp(logit+bias)
__device__ __align__(256) float g_tsum[B_ * NTILE];

// ---------------- helpers ----------------
__device__ __forceinline__ float fsig(float x) {
    return __fdividef(1.0f, 1.0f + __expf(-x));
}
__device__ __forceinline__ float ftanh(float x) {
    float e = __expf(2.0f * x);
    return 1.0f - __fdividef(2.0f, 1.0f + e);
}
__device__ __forceinline__ uint32_t pkbf2(float a, float b) {
    uint32_t r;
    asm("cvt.rn.bf16x2.f32 %0, %2, %1;" : "=r"(r) : "f"(a), "f"(b));
    return r;
}
// PDL primitives
__device__ __forceinline__ void gdep_wait() {
    asm volatile("griddepcontrol.wait;" ::: "memory");
}
__device__ __forceinline__ void gdep_launch() {
    asm volatile("griddepcontrol.launch_dependents;");
}

// =============== K0: zero scratch + prep transposed activations (fused) ===============
__global__ void k_prep_zero(const int* __restrict__ y_t, const float* __restrict__ c_t_1,
                            const float* __restrict__ embed_W, const float* __restrict__ h0) {
    gdep_launch();
    int bid = blockIdx.x, t = threadIdx.x;     // grid 512 x 256
    int i = bid * 256 + t;
    if (i < E_ * B_)      g_xT[i] = 0.0f;
    if (i < 4 * H_ * B_)  g_gatesT[i] = 0.0f;
    if (i < 2 * H_ * B_)  { g_decT[i] = 0.0f; g_ctT[i] = 0.0f; }
    if (i < H_ * B_)      g_hidT[i] = 0.0f;
    if (bid < B_) {
        int b = bid;
        for (int k = t; k < 512; k += 256) g_prepT[k * 128 + b] = c_t_1[b * 512 + k];
        int y = y_t[b];
        if (t < 128) g_prepT[(512 + t) * 128 + b] = embed_W[y * 128 + t];
        g_h0T[t * 128 + b] = h0[b * 256 + t];
    }
}

// =============== unified small GEMM (1 chunk of 64 k per block) ===============
__global__ void __launch_bounds__(256) k_gemm(
    const float* __restrict__ actA, const float* __restrict__ WA, int sWA, int KA,
    const float* __restrict__ actB, const float* __restrict__ WB, int sWB,
    const float* __restrict__ bias1, const float* __restrict__ bias2,
    float* __restrict__ outT)
{
    __shared__ float s_act[32][65];
    __shared__ float s_w[32][64];
    int tid = threadIdx.x;
    int lane = tid & 31, wp = tid >> 5;
    int j0 = blockIdx.x * 32;
    int b  = blockIdx.y * 32 + lane;
    int k0 = blockIdx.z * 64;

    const float* asrc; const float* wsrc; int ws; int kr;
    if (k0 < KA) { asrc = actA; wsrc = WA; ws = sWA; kr = k0; }
    else         { asrc = actB; wsrc = WB; ws = sWB; kr = k0 - KA; }
    // stage W pre-wait (inputs; overlaps predecessor tail)
    {
        int idx = tid * 2;
        int j = idx >> 4, f = (idx & 15) * 4;
        float4 v = *(const float4*)&wsrc[(j0 + j) * ws + kr + f];
        *(float4*)&s_w[j][f] = v;
        idx++;
        j = idx >> 4; f = (idx & 15) * 4;
        v = *(const float4*)&wsrc[(j0 + j) * ws + kr + f];
        *(float4*)&s_w[j][f] = v;
    }
    gdep_wait();
    gdep_launch();
#pragma unroll
    for (int r = 0; r < 8; r++) {
        int k = r * 8 + wp;
        s_act[lane][k] = asrc[(kr + k) * 128 + b];
    }
    __syncthreads();
    float acc0 = 0.0f, acc1 = 0.0f, acc2 = 0.0f, acc3 = 0.0f;
#pragma unroll
    for (int kk = 0; kk < 64; kk += 4) {
        float a0 = s_act[lane][kk + 0];
        float a1 = s_act[lane][kk + 1];
        float a2 = s_act[lane][kk + 2];
        float a3 = s_act[lane][kk + 3];
        float4 w0 = *(const float4*)&s_w[wp * 4 + 0][kk];
        float4 w1 = *(const float4*)&s_w[wp * 4 + 1][kk];
        float4 w2 = *(const float4*)&s_w[wp * 4 + 2][kk];
        float4 w3 = *(const float4*)&s_w[wp * 4 + 3][kk];
        acc0 += w0.x * a0 + w0.y * a1 + w0.z * a2 + w0.w * a3;
        acc1 += w1.x * a0 + w1.y * a1 + w1.z * a2 + w1.w * a3;
        acc2 += w2.x * a0 + w2.y * a1 + w2.z * a2 + w2.w * a3;
        acc3 += w3.x * a0 + w3.y * a1 + w3.z * a2 + w3.w * a3;
    }
    int j = j0 + wp * 4;
    if (blockIdx.z == 0 && bias1) {
        acc0 += bias1[j + 0]; acc1 += bias1[j + 1]; acc2 += bias1[j + 2]; acc3 += bias1[j + 3];
        if (bias2) {
            acc0 += bias2[j + 0]; acc1 += bias2[j + 1]; acc2 += bias2[j + 2]; acc3 += bias2[j + 3];
        }
    }
    atomicAdd(&outT[(j + 0) * 128 + b], acc0);
    atomicAdd(&outT[(j + 1) * 128 + b], acc1);
    atomicAdd(&outT[(j + 2) * 128 + b], acc2);
    atomicAdd(&outT[(j + 3) * 128 + b], acc3);
}

// =============== K3: LSTM pointwise (wide grid) ===============
__global__ void k_lstm(const float* __restrict__ c0, float* __restrict__ outp) {
    gdep_wait();
    gdep_launch();
    int i = blockIdx.x * 64 + threadIdx.x;
    int t = i >> 7, b = i & 127;
    float gi = g_gatesT[i];
    float gf = g_gatesT[i + 32768];
    float gg = g_gatesT[i + 65536];
    float go = g_gatesT[i + 98304];
    float c0v = c0[b * 256 + t];
    float cc = fsig(gf) * c0v + fsig(gi) * ftanh(gg);
    float hh = fsig(go) * ftanh(cc);
    outp[O_H + b * 256 + t] = hh;
    outp[O_C + b * 256 + t] = cc;
    g_hcT[t * 128 + b] = hh;
    g_hcT[(256 + t) * 128 + b] = cc;
}

// =============== K5: attention energy (streams enc_feats) ===============
__global__ void k_energy(const float* __restrict__ enc_feats,
                         const float* __restrict__ coverage,
                         const float* __restrict__ Wc_W, const float* __restrict__ v_W) {
    int idx0 = blockIdx.x * 8;
    int b = idx0 >> 10;
    __shared__ float sdec[512], swc[512], sv[512];
    int tid = threadIdx.x;
    for (int i = tid; i < 512; i += 256) {
        swc[i]  = Wc_W[i];
        sv[i]   = v_W[i];
    }
    gdep_wait();
    gdep_launch();
    for (int i = tid; i < 512; i += 256) sdec[i] = g_decT[i * 128 + b];
    __syncthreads();
    int w = tid >> 5, lane = tid & 31;
    int idx = idx0 + w;
    float cov = coverage[idx];
    const float* base = enc_feats + (size_t)idx * 512;
    float e = 0.0f;
#pragma unroll
    for (int c = 0; c < 4; c++) {
        int d0 = c * 128 + lane * 4;
        float4 f  = *(const float4*)(base + d0);
        float4 dv = *(const float4*)(sdec + d0);
        float4 wv = *(const float4*)(swc + d0);
        float4 vv = *(const float4*)(sv + d0);
        e += ftanh(f.x + dv.x + cov * wv.x) * vv.x;
        e += ftanh(f.y + dv.y + cov * wv.y) * vv.y;
        e += ftanh(f.z + dv.z + cov * wv.z) * vv.z;
        e += ftanh(f.w + dv.w + cov * wv.w) * vv.w;
    }
#pragma unroll
    for (int o = 16; o; o >>= 1) e += __shfl_xor_sync(0xffffffffu, e, o);
    if (lane == 0) g_energy[idx] = e;
}

// =============== K6: softmax over L ===============
__global__ void k_softmax_a(const float* __restrict__ mask, const float* __restrict__ coverage,
                            float* __restrict__ outp) {
    gdep_wait();
    gdep_launch();
    int b = blockIdx.x, tid = threadIdx.x;
    __shared__ float red[256];
    float e[4];
#pragma unroll
    for (int j = 0; j < 4; j++) e[j] = g_energy[b * 1024 + tid + j * 256];
    float m = fmaxf(fmaxf(e[0], e[1]), fmaxf(e[2], e[3]));
    red[tid] = m; __syncthreads();
    for (int s = 128; s > 0; s >>= 1) { if (tid < s) red[tid] = fmaxf(red[tid], red[tid + s]); __syncthreads(); }
    float M = red[0]; __syncthreads();
    float ev[4], sum = 0.0f;
#pragma unroll
    for (int j = 0; j < 4; j++) {
        ev[j] = __expf(e[j] - M) * mask[b * 1024 + tid + j * 256];
        sum += ev[j];
    }
    red[tid] = sum; __syncthreads();
    for (int s = 128; s > 0; s >>= 1) { if (tid < s) red[tid] += red[tid + s]; __syncthreads(); }
    float inv = __fdividef(1.0f, red[0]);
#pragma unroll
    for (int j = 0; j < 4; j++) {
        int i = b * 1024 + tid + j * 256;
        float a = ev[j] * inv;
        outp[O_A + i] = a;
        outp[O_COV + i] = coverage[i] + a;
    }
}

// =============== K7: c_t partials (streams enc_outs) — accumulates c_t directly ===============
__global__ void k_ctx(const float* __restrict__ enc_outs, const float* __restrict__ outp) {
    gdep_wait();
    gdep_launch();
    int chunk = blockIdx.x, b = blockIdx.y;
    __shared__ float sa[64];
    int tid = threadIdx.x;
    if (tid < 64) sa[tid] = outp[O_A + b * 1024 + chunk * 64 + tid];
    __syncthreads();
    const float2* p = (const float2*)(enc_outs + ((size_t)b * 1024 + chunk * 64) * 512);
    float2 acc = make_float2(0.0f, 0.0f);
#pragma unroll 8
    for (int i = 0; i < 64; i++) {
        float2 v = p[i * 256 + tid];
        float a = sa[i];
        acc.x += a * v.x;
        acc.y += a * v.y;
    }
    // a is already normalized -> partials sum directly to c_t
    atomicAdd(&g_ctT[(2 * tid) * 128 + b], acc.x);
    atomicAdd(&g_ctT[(2 * tid + 1) * 128 + b], acc.y);
}

// =============== K8: c_t copy-out + p_gen (runs OFF critical path on s2) ===============
__global__ void k_finalize(const float* __restrict__ pgen_W, const float* __restrict__ pgen_b,
                           float* __restrict__ outp) {
    gdep_wait();
    gdep_launch();
    int b = blockIdx.x, tid = threadIdx.x;     // 512
    __shared__ float red[512];
    float ct = g_ctT[tid * 128 + b];
    outp[O_CT + b * 512 + tid] = ct;
    float p = pgen_W[tid] * ct;
    float z2 = (tid < 256) ? outp[O_H + b * 256 + tid] : outp[O_C + b * 256 + (tid - 256)];
    p += pgen_W[512 + tid] * z2;
    if (tid < 128) p += pgen_W[1024 + tid] * g_xT[tid * 128 + b];
    red[tid] = p; __syncthreads();
    for (int st = 256; st > 0; st >>= 1) { if (tid < st) red[tid] += red[tid + st]; __syncthreads(); }
    if (tid == 0) outp[O_PG + b] = fsig(red[0] + pgen_b[0]);
}

// =============== K10: pipelined logits GEMM on tensor cores (tile loop) ===============
// Logits are tiny (|logit| << 1): softmax needs no max-subtraction.
// Store exp(logit+bias) directly; emit per-row tile sums only.
// Grid LGRID=296 (2/SM); each block loops tiles (tile += LGRID), reusing staged A.
#define SA_STRIDE 132
#define SB_STRIDE 20
#define SB_WORDS  (128 * SB_STRIDE)
#define SMEM_LOGITS ((128 * SA_STRIDE + 2 * SB_WORDS) * 4 + 128 * 4 + 128 * 4 * 4)

__global__ void __launch_bounds__(256) k_logits_mma(const float* __restrict__ outW,
                                                    const float* __restrict__ outb) {
    extern __shared__ uint32_t smem_dyn[];
    uint32_t* sA = smem_dyn;
    uint32_t* sB = sA + 128 * SA_STRIDE;
    float* s_bias = (float*)(sB + 2 * SB_WORDS);
    float* s_red  = s_bias + 128;                 // [128][4]

    int tid = threadIdx.x;
    int lane = tid & 31, wid = tid >> 5;
    int wm = wid >> 2, wn = wid & 3;
    int g = lane >> 2, tg = lane & 3;

    const int tile0 = blockIdx.x;

    // ---- pre-wait: inputs only (first tile's bias + first B chunk) ----
    {
        int v00 = tile0 * 128;
        if (tid < 128) s_bias[tid] = (v00 + tid < V_) ? outb[v00 + tid] : 0.0f;
    }
    float4 pw[4];
#pragma unroll
    for (int r = 0; r < 4; r++) {
        int idx = r * 256 + tid;
        int v = tile0 * 128 + (idx >> 3), f = idx & 7;
        pw[r] = (v < V_) ? *(const float4*)&outW[(size_t)v * 256 + f * 4]
                         : make_float4(0.f, 0.f, 0.f, 0.f);
    }
    gdep_wait();
    gdep_launch();
    // ---- stage A once (tile-independent) ----
#pragma unroll 8
    for (int r = 0; r < 64; r++) {
        int idx = r * 256 + tid;
        int b = idx & 127, w = idx >> 7;
        float lo = g_hidT[(2 * w) * 128 + b];
        float hi = g_hidT[(2 * w + 1) * 128 + b];
        sA[b * SA_STRIDE + w] = pkbf2(lo, hi);
    }

    for (int tile = tile0; tile < NTILE; tile += LGRID) {
        const int v0 = tile * 128;
        if (tile != tile0) {
            __syncthreads();   // previous tile fully done (epilogue reads of s_bias/s_red)
            if (tid < 128) s_bias[tid] = (v0 + tid < V_) ? outb[v0 + tid] : 0.0f;
#pragma unroll
            for (int r = 0; r < 4; r++) {
                int idx = r * 256 + tid;
                int v = v0 + (idx >> 3), f = idx & 7;
                pw[r] = (v < V_) ? *(const float4*)&outW[(size_t)v * 256 + f * 4]
                                 : make_float4(0.f, 0.f, 0.f, 0.f);
            }
        }
#pragma unroll
        for (int r = 0; r < 4; r++) {
            int idx = r * 256 + tid;
            int v = idx >> 3, f = idx & 7;
            sB[v * SB_STRIDE + f * 2]     = pkbf2(pw[r].x, pw[r].y);
            sB[v * SB_STRIDE + f * 2 + 1] = pkbf2(pw[r].z, pw[r].w);
        }
        __syncthreads();

        float acc[4][4][4];
#pragma unroll
        for (int mt = 0; mt < 4; mt++)
#pragma unroll
            for (int nt = 0; nt < 4; nt++)
#pragma unroll
                for (int q = 0; q < 4; q++) acc[mt][nt][q] = 0.0f;

#pragma unroll 1
        for (int it = 0; it < 8; it++) {
            if (it < 7) {
                int k0n = (it + 1) * 32;
#pragma unroll
                for (int r = 0; r < 4; r++) {
                    int idx = r * 256 + tid;
                    int v = v0 + (idx >> 3), f = idx & 7;
                    pw[r] = (v < V_) ? *(const float4*)&outW[(size_t)v * 256 + k0n + f * 4]
                                     : make_float4(0.f, 0.f, 0.f, 0.f);
                }
            }
            const uint32_t* sBp = sB + (it & 1) * SB_WORDS;
            int aw = it * 16;
#pragma unroll
            for (int kk = 0; kk < 2; kk++) {
                int kw = kk * 8 + tg;
                uint32_t a[4][4];
#pragma unroll
                for (int mt = 0; mt < 4; mt++) {
                    int r0 = wm * 64 + mt * 16 + g;
                    a[mt][0] = sA[r0 * SA_STRIDE + aw + kw];
                    a[mt][1] = sA[(r0 + 8) * SA_STRIDE + aw + kw];
                    a[mt][2] = sA[r0 * SA_STRIDE + aw + kw + 4];
                    a[mt][3] = sA[(r0 + 8) * SA_STRIDE + aw + kw + 4];
                }
#pragma unroll
                for (int nt = 0; nt < 4; nt++) {
                    int n0 = wn * 32 + nt * 8 + g;
                    uint32_t b0 = sBp[n0 * SB_STRIDE + kw];
                    uint32_t b1 = sBp[n0 * SB_STRIDE + kw + 4];
#pragma unroll
                    for (int mt = 0; mt < 4; mt++) {
                        asm volatile(
                            "mma.sync.aligned.m16n8k16.row.col.f32.bf16.bf16.f32 "
                            "{%0,%1,%2,%3},{%4,%5,%6,%7},{%8,%9},{%0,%1,%2,%3};"
                            : "+f"(acc[mt][nt][0]), "+f"(acc[mt][nt][1]),
                              "+f"(acc[mt][nt][2]), "+f"(acc[mt][nt][3])
                            : "r"(a[mt][0]), "r"(a[mt][1]), "r"(a[mt][2]), "r"(a[mt][3]),
                              "r"(b0), "r"(b1));
                    }
                }
            }
            if (it < 7) {
                uint32_t* sBn = sB + ((it + 1) & 1) * SB_WORDS;
#pragma unroll
                for (int r = 0; r < 4; r++) {
                    int idx = r * 256 + tid;
                    int v = idx >> 3, f = idx & 7;
                    sBn[v * SB_STRIDE + f * 2]     = pkbf2(pw[r].x, pw[r].y);
                    sBn[v * SB_STRIDE + f * 2 + 1] = pkbf2(pw[r].z, pw[r].w);
                }
            }
            __syncthreads();
        }

        // ---- epilogue: exp(logit+bias) stored; per-row tile sums ----
        int cbase = wn * 32 + tg * 2;
        bool val[4];
#pragma unroll
        for (int nt = 0; nt < 4; nt++) val[nt] = (v0 + cbase + nt * 8) < V_;
#pragma unroll
        for (int mt = 0; mt < 4; mt++) {
#pragma unroll
            for (int h = 0; h < 2; h++) {
                int row = wm * 64 + mt * 16 + g + h * 8;
                float s = 0.0f;
#pragma unroll
                for (int nt = 0; nt < 4; nt++) {
                    if (val[nt]) {
                        float bv0 = s_bias[cbase + nt * 8];
                        float bv1 = s_bias[cbase + nt * 8 + 1];
                        float e0 = __expf(acc[mt][nt][2 * h]     + bv0);
                        float e1 = __expf(acc[mt][nt][2 * h + 1] + bv1);
                        *(float2*)&g_logits[(size_t)row * V_ + v0 + cbase + nt * 8] = make_float2(e0, e1);
                        s += e0 + e1;
                    }
                }
                s += __shfl_xor_sync(0xffffffffu, s, 1);
                s += __shfl_xor_sync(0xffffffffu, s, 2);
                if (tg == 0) s_red[row * 4 + wn] = s;
            }
        }
        __syncthreads();
        if (tid < 128) {
            float s = s_red[tid * 4 + 0] + s_red[tid * 4 + 1] + s_red[tid * 4 + 2] + s_red[tid * 4 + 3];
            g_tsum[tid * NTILE + tile] = s;
        }
    }
}

// =============== K12: final vocab dist (float4) — combine fused in-block ===============
__global__ void k_final_vocab(const float* __restrict__ extra_zeros, float* __restrict__ outp) {
    gdep_wait();
    gdep_launch();
    int b = blockIdx.y;
    int tid = threadIdx.x;
    __shared__ float red[256];
    __shared__ float sSc;
    float s = 0.0f;
    for (int i = tid; i < NTILE; i += 256) s += g_tsum[b * NTILE + i];
    red[tid] = s; __syncthreads();
    for (int st = 128; st > 0; st >>= 1) { if (tid < st) red[tid] += red[tid + st]; __syncthreads(); }
    if (tid == 0) sSc = __fdividef(outp[O_PG + b], red[0]);
    __syncthreads();
    float sc = sSc;
    int q = blockIdx.x * 256 + tid;
    if (q < 12500) {
        float4 lg = *(const float4*)&g_logits[(size_t)b * V_ + q * 4];
        float4 o;
        o.x = sc * lg.x;
        o.y = sc * lg.y;
        o.z = sc * lg.z;
        o.w = sc * lg.w;
        *(float4*)&outp[O_FD + (size_t)b * VX_ + q * 4] = o;
    } else if (q < 12525) {
        int v = q * 4 - V_;
        float4 z = *(const float4*)&extra_zeros[b * X_ + v];
        *(float4*)&outp[O_FD + (size_t)b * VX_ + q * 4] = z;
    }
}

// =============== K13: pointer scatter-add ===============
__global__ void k_scatter(const int* __restrict__ ext_vocab, float* __restrict__ outp) {
    gdep_wait();
    gdep_launch();
    int i = blockIdx.x * 256 + threadIdx.x;
    int b = i >> 10;
    float pg = outp[O_PG + b];
    float av = outp[O_A + i];
    atomicAdd(&outp[O_FD + b * VX_ + ext_vocab[i]], (1.0f - pg) * av);
}

// ---------------- PDL launch helper (main stream) ----------------
template <typename... Args>
static inline void pdl_launch(dim3 g, dim3 b, size_t shm,
                              void (*f)(Args...), Args... a) {
    cudaLaunchConfig_t cfg = {};
    cfg.gridDim = g; cfg.blockDim = b; cfg.dynamicSmemBytes = shm; cfg.stream = 0;
    cudaLaunchAttribute at[1];
    at[0].id = cudaLaunchAttributeProgrammaticStreamSerialization;
    at[0].val.programmaticStreamSerializationAllowed = 1;
    cfg.attrs = at; cfg.numAttrs = 1;
    cudaLaunchKernelEx(&cfg, f, a...);
}

// ======================================================================
extern "C" void kernel_launch(void* const* d_in, const int* in_sizes, int n_in,
                              void* d_out, int out_size) {
    (void)in_sizes; (void)n_in; (void)out_size;
    const int*   y_t       = (const int*)d_in[0];
    const float* h0        = (const float*)d_in[1];
    const float* c0        = (const float*)d_in[2];
    const float* enc_outs  = (const float*)d_in[3];
    const float* enc_feats = (const float*)d_in[4];
    const float* mask      = (const float*)d_in[5];
    const float* c_t_1     = (const float*)d_in[6];
    const float* extra_z   = (const float*)d_in[7];
    const int*   ext_vocab = (const int*)d_in[8];
    const float* coverage  = (const float*)d_in[9];
    const float* embed_W   = (const float*)d_in[10];
    const float* Wih       = (const float*)d_in[11];
    const float* Whh       = (const float*)d_in[12];
    const float* bih       = (const float*)d_in[13];
    const float* bhh       = (const float*)d_in[14];
    const float* xctx_W    = (const float*)d_in[15];
    const float* xctx_b    = (const float*)d_in[16];
    const float* Ws_W      = (const float*)d_in[17];
    const float* Ws_b      = (const float*)d_in[18];
    const float* Wc_W      = (const float*)d_in[19];
    const float* v_W       = (const float*)d_in[20];
    const float* pgen_W    = (const float*)d_in[21];
    const float* pgen_b    = (const float*)d_in[22];
    const float* proj_W    = (const float*)d_in[23];
    const float* proj_b    = (const float*)d_in[24];
    const float* out_W     = (const float*)d_in[25];
    const float* out_b     = (const float*)d_in[26];
    float* outp = (float*)d_out;

    float* d_xT;     cudaGetSymbolAddress((void**)&d_xT, g_xT);
    float* d_gatesT; cudaGetSymbolAddress((void**)&d_gatesT, g_gatesT);
    float* d_hcT;    cudaGetSymbolAddress((void**)&d_hcT, g_hcT);
    float* d_decT;   cudaGetSymbolAddress((void**)&d_decT, g_decT);
    float* d_ctT;    cudaGetSymbolAddress((void**)&d_ctT, g_ctT);
    float* d_hidT;   cudaGetSymbolAddress((void**)&d_hidT, g_hidT);
    float* d_prepT;  cudaGetSymbolAddress((void**)&d_prepT, g_prepT);
    float* d_h0T;    cudaGetSymbolAddress((void**)&d_h0T, g_h0T);
    const float* cnull = nullptr;

    cudaFuncSetAttribute(k_logits_mma, cudaFuncAttributeMaxDynamicSharedMemorySize, SMEM_LOGITS);

    // side stream + events for fork-join capture (host handles only; no device mem)
    cudaStream_t s2;
    cudaStreamCreateWithFlags(&s2, cudaStreamNonBlocking);
    cudaEvent_t ev0, evG, ev1, ev2, evC, evF;
    cudaEventCreateWithFlags(&ev0, cudaEventDisableTiming);
    cudaEventCreateWithFlags(&evG, cudaEventDisableTiming);
    cudaEventCreateWithFlags(&ev1, cudaEventDisableTiming);
    cudaEventCreateWithFlags(&ev2, cudaEventDisableTiming);
    cudaEventCreateWithFlags(&evC, cudaEventDisableTiming);
    cudaEventCreateWithFlags(&evF, cudaEventDisableTiming);

    k_prep_zero<<<512, 256>>>(y_t, c_t_1, embed_W, h0);

    // fork: gates h0-half (K=256, biases) on s2, overlapping the x GEMM on main
    cudaEventRecord(ev0, 0);
    cudaStreamWaitEvent(s2, ev0, 0);
    k_gemm<<<dim3(32, 4, 4), 256, 0, s2>>>(d_h0T, Whh, 256, 256,
                                           cnull, cnull, 0, bih, bhh, d_gatesT);
    cudaEventRecord(evG, s2);

    // x = [c_t_1, emb] @ xctx_W.T + xctx_b   (K=640 -> 10 chunks)
    pdl_launch(dim3(4, 4, 10), dim3(256), 0, k_gemm,
               (const float*)d_prepT, xctx_W, 640, 640,
               cnull, cnull, 0, xctx_b, cnull, (float*)d_xT);
    // gates x-half (K=128 -> 2 chunks, no bias — applied in h0-half)
    pdl_launch(dim3(32, 4, 2), dim3(256), 0, k_gemm,
               (const float*)d_xT, Wih, 128, 128,
               cnull, cnull, 0, cnull, cnull, (float*)d_gatesT);
    // join both gates halves before lstm
    cudaStreamWaitEvent(0, evG, 0);
    pdl_launch(dim3(512), dim3(64), 0, k_lstm, c0, outp);

    // fork: h-half of hid GEMM overlaps the attention phase
    cudaEventRecord(ev1, 0);
    cudaStreamWaitEvent(s2, ev1, 0);
    k_gemm<<<dim3(8, 4, 4), 256, 0, s2>>>(d_hcT, proj_W, 768, 256,
                                          cnull, cnull, 0, proj_b, cnull, d_hidT);
    cudaEventRecord(ev2, s2);

    // dec = [h,c]@Ws_W.T + Ws_b              (K=512 -> 8 chunks)
    pdl_launch(dim3(16, 4, 8), dim3(256), 0, k_gemm,
               (const float*)d_hcT, Ws_W, 512, 512,
               cnull, cnull, 0, Ws_b, cnull, (float*)d_decT);
    pdl_launch(dim3(B_ * L_ / 8), dim3(256), 0, k_energy,
               enc_feats, coverage, Wc_W, v_W);
    pdl_launch(dim3(B_), dim3(256), 0, k_softmax_a, mask, coverage, outp);
    pdl_launch(dim3(16, B_), dim3(256), 0, k_ctx, enc_outs, (const float*)outp);

    // fork: finalize (c_t copy-out + p_gen) on s2 — off the critical path
    cudaEventRecord(evC, 0);
    cudaStreamWaitEvent(s2, evC, 0);
    k_finalize<<<B_, 512, 0, s2>>>(pgen_W, pgen_b, outp);
    cudaEventRecord(evF, s2);

    // ct-half of hid GEMM (K=512 -> 8 chunks), no bias (added in h-half)
    pdl_launch(dim3(8, 4, 8), dim3(256), 0, k_gemm,
               (const float*)d_ctT, (const float*)(proj_W + 256), 768, 512,
               cnull, cnull, 0, cnull, cnull, (float*)d_hidT);
    // join: logits needs both hid halves
    cudaStreamWaitEvent(0, ev2, 0);
    pdl_launch(dim3(LGRID), dim3(256), (size_t)SMEM_LOGITS, k_logits_mma, out_W, out_b);
    // join: final_vocab needs p_gen from finalize (s2)
    cudaStreamWaitEvent(0, evF, 0);
    pdl_launch(dim3(49, B_), dim3(256), 0, k_final_vocab, extra_z, outp);
    pdl_launch(dim3(B_ * L_ / 256), dim3(256), 0, k_scatter, ext_vocab, outp);
}

// round 16
// speedup vs baseline: 1.3003x; 1.0560x over previous
#include <cuda_runtime.h>
#include <cuda_bf16.h>
#include <cstdint>

#define B_ 128
#define L_ 1024
#define H_ 256
#define E_ 128
#define V_ 50000
#define X_ 100
#define VX_ 50100
#define NTILE 391
#define LGRID 296

// d_out float offsets (tuple order: final_dist, h, c, c_t, a, p_gen, coverage_next)
#define O_FD  0
#define O_H   6412800
#define O_C   6445568
#define O_CT  6478336
#define O_A   6543872
#define O_PG  6674944
#define O_COV 6675072

// ---------------- static device scratch (no allocations) ----------------
__device__ __align__(256) float g_prepT[640 * B_];
__device__ __align__(256) float g_h0T[256 * B_];
__device__ __align__(256) float g_xT[E_ * B_];
__device__ __align__(256) float g_gatesT[4 * H_ * B_];
__device__ __align__(256) float g_hcT[2 * H_ * B_];
__device__ __align__(256) float g_decT[2 * H_ * B_];
__device__ __align__(256) float g_ctT[2 * H_ * B_];       // c_t accumulated by k_ctx
__device__ __align__(256) float g_hidT[H_ * B_];          // [k][b]
__device__ __align__(256) float g_energy[B_ * L_];
__device__ __align__(256) float g_logits[B_ * V_];        // holds exp(logit+bias)
__device__ __align__(256) float g_tsum[B_ * NTILE];

// ---------------- helpers ----------------
__device__ __forceinline__ float fsig(float x) {
    return __fdividef(1.0f, 1.0f + __expf(-x));
}
__device__ __forceinline__ float ftanh(float x) {
    float e = __expf(2.0f * x);
    return 1.0f - __fdividef(2.0f, 1.0f + e);
}
__device__ __forceinline__ uint32_t pkbf2(float a, float b) {
    uint32_t r;
    asm("cvt.rn.bf16x2.f32 %0, %2, %1;" : "=r"(r) : "f"(a), "f"(b));
    return r;
}
// PDL primitives
__device__ __forceinline__ void gdep_wait() {
    asm volatile("griddepcontrol.wait;" ::: "memory");
}
__device__ __forceinline__ void gdep_launch() {
    asm volatile("griddepcontrol.launch_dependents;");
}

// =============== K0: zero scratch + prep transposed activations (fused) ===============
__global__ void k_prep_zero(const int* __restrict__ y_t, const float* __restrict__ c_t_1,
                            const float* __restrict__ embed_W, const float* __restrict__ h0) {
    gdep_launch();
    int bid = blockIdx.x, t = threadIdx.x;     // grid 512 x 256
    int i = bid * 256 + t;
    if (i < E_ * B_)      g_xT[i] = 0.0f;
    if (i < 4 * H_ * B_)  g_gatesT[i] = 0.0f;
    if (i < 2 * H_ * B_)  { g_decT[i] = 0.0f; g_ctT[i] = 0.0f; }
    if (i < H_ * B_)      g_hidT[i] = 0.0f;
    if (bid < B_) {
        int b = bid;
        for (int k = t; k < 512; k += 256) g_prepT[k * 128 + b] = c_t_1[b * 512 + k];
        int y = y_t[b];
        if (t < 128) g_prepT[(512 + t) * 128 + b] = embed_W[y * 128 + t];
        g_h0T[t * 128 + b] = h0[b * 256 + t];
    }
}

// =============== unified small GEMM (1 chunk of 64 k per block) ===============
__global__ void __launch_bounds__(256) k_gemm(
    const float* __restrict__ actA, const float* __restrict__ WA, int sWA, int KA,
    const float* __restrict__ actB, const float* __restrict__ WB, int sWB,
    const float* __restrict__ bias1, const float* __restrict__ bias2,
    float* __restrict__ outT)
{
    __shared__ float s_act[32][65];
    __shared__ float s_w[32][64];
    int tid = threadIdx.x;
    int lane = tid & 31, wp = tid >> 5;
    int j0 = blockIdx.x * 32;
    int b  = blockIdx.y * 32 + lane;
    int k0 = blockIdx.z * 64;

    const float* asrc; const float* wsrc; int ws; int kr;
    if (k0 < KA) { asrc = actA; wsrc = WA; ws = sWA; kr = k0; }
    else         { asrc = actB; wsrc = WB; ws = sWB; kr = k0 - KA; }
    // stage W pre-wait (inputs; overlaps predecessor tail)
    {
        int idx = tid * 2;
        int j = idx >> 4, f = (idx & 15) * 4;
        float4 v = *(const float4*)&wsrc[(j0 + j) * ws + kr + f];
        *(float4*)&s_w[j][f] = v;
        idx++;
        j = idx >> 4; f = (idx & 15) * 4;
        v = *(const float4*)&wsrc[(j0 + j) * ws + kr + f];
        *(float4*)&s_w[j][f] = v;
    }
    gdep_wait();
    gdep_launch();
#pragma unroll
    for (int r = 0; r < 8; r++) {
        int k = r * 8 + wp;
        s_act[lane][k] = asrc[(kr + k) * 128 + b];
    }
    __syncthreads();
    float acc0 = 0.0f, acc1 = 0.0f, acc2 = 0.0f, acc3 = 0.0f;
#pragma unroll
    for (int kk = 0; kk < 64; kk += 4) {
        float a0 = s_act[lane][kk + 0];
        float a1 = s_act[lane][kk + 1];
        float a2 = s_act[lane][kk + 2];
        float a3 = s_act[lane][kk + 3];
        float4 w0 = *(const float4*)&s_w[wp * 4 + 0][kk];
        float4 w1 = *(const float4*)&s_w[wp * 4 + 1][kk];
        float4 w2 = *(const float4*)&s_w[wp * 4 + 2][kk];
        float4 w3 = *(const float4*)&s_w[wp * 4 + 3][kk];
        acc0 += w0.x * a0 + w0.y * a1 + w0.z * a2 + w0.w * a3;
        acc1 += w1.x * a0 + w1.y * a1 + w1.z * a2 + w1.w * a3;
        acc2 += w2.x * a0 + w2.y * a1 + w2.z * a2 + w2.w * a3;
        acc3 += w3.x * a0 + w3.y * a1 + w3.z * a2 + w3.w * a3;
    }
    int j = j0 + wp * 4;
    if (blockIdx.z == 0 && bias1) {
        acc0 += bias1[j + 0]; acc1 += bias1[j + 1]; acc2 += bias1[j + 2]; acc3 += bias1[j + 3];
        if (bias2) {
            acc0 += bias2[j + 0]; acc1 += bias2[j + 1]; acc2 += bias2[j + 2]; acc3 += bias2[j + 3];
        }
    }
    atomicAdd(&outT[(j + 0) * 128 + b], acc0);
    atomicAdd(&outT[(j + 1) * 128 + b], acc1);
    atomicAdd(&outT[(j + 2) * 128 + b], acc2);
    atomicAdd(&outT[(j + 3) * 128 + b], acc3);
}

// =============== K3: LSTM pointwise (wide grid) ===============
__global__ void k_lstm(const float* __restrict__ c0, float* __restrict__ outp) {
    gdep_wait();
    gdep_launch();
    int i = blockIdx.x * 64 + threadIdx.x;
    int t = i >> 7, b = i & 127;
    float gi = g_gatesT[i];
    float gf = g_gatesT[i + 32768];
    float gg = g_gatesT[i + 65536];
    float go = g_gatesT[i + 98304];
    float c0v = c0[b * 256 + t];
    float cc = fsig(gf) * c0v + fsig(gi) * ftanh(gg);
    float hh = fsig(go) * ftanh(cc);
    outp[O_H + b * 256 + t] = hh;
    outp[O_C + b * 256 + t] = cc;
    g_hcT[t * 128 + b] = hh;
    g_hcT[(256 + t) * 128 + b] = cc;
}

// =============== K5: attention energy (16 rows/block: halves staging traffic) ===============
__global__ void k_energy(const float* __restrict__ enc_feats,
                         const float* __restrict__ coverage,
                         const float* __restrict__ Wc_W, const float* __restrict__ v_W) {
    int idx0 = blockIdx.x * 16;                 // grid B*L/16 = 8192
    int b = idx0 >> 10;                         // 16 | 1024 -> uniform per block
    __shared__ float sdec[512], swc[512], sv[512];
    int tid = threadIdx.x;
    for (int i = tid; i < 512; i += 256) {
        swc[i]  = Wc_W[i];
        sv[i]   = v_W[i];
    }
    gdep_wait();
    gdep_launch();
    for (int i = tid; i < 512; i += 256) sdec[i] = g_decT[i * 128 + b];
    __syncthreads();
    int w = tid >> 5, lane = tid & 31;
#pragma unroll
    for (int r = 0; r < 2; r++) {
        int idx = idx0 + r * 8 + w;
        float cov = coverage[idx];
        const float* base = enc_feats + (size_t)idx * 512;
        float e = 0.0f;
#pragma unroll
        for (int c = 0; c < 4; c++) {
            int d0 = c * 128 + lane * 4;
            float4 f  = *(const float4*)(base + d0);
            float4 dv = *(const float4*)(sdec + d0);
            float4 wv = *(const float4*)(swc + d0);
            float4 vv = *(const float4*)(sv + d0);
            e += ftanh(f.x + dv.x + cov * wv.x) * vv.x;
            e += ftanh(f.y + dv.y + cov * wv.y) * vv.y;
            e += ftanh(f.z + dv.z + cov * wv.z) * vv.z;
            e += ftanh(f.w + dv.w + cov * wv.w) * vv.w;
        }
#pragma unroll
        for (int o = 16; o; o >>= 1) e += __shfl_xor_sync(0xffffffffu, e, o);
        if (lane == 0) g_energy[idx] = e;
    }
}

// =============== K6: softmax over L ===============
__global__ void k_softmax_a(const float* __restrict__ mask, const float* __restrict__ coverage,
                            float* __restrict__ outp) {
    gdep_wait();
    gdep_launch();
    int b = blockIdx.x, tid = threadIdx.x;
    __shared__ float red[256];
    float e[4];
#pragma unroll
    for (int j = 0; j < 4; j++) e[j] = g_energy[b * 1024 + tid + j * 256];
    float m = fmaxf(fmaxf(e[0], e[1]), fmaxf(e[2], e[3]));
    red[tid] = m; __syncthreads();
    for (int s = 128; s > 0; s >>= 1) { if (tid < s) red[tid] = fmaxf(red[tid], red[tid + s]); __syncthreads(); }
    float M = red[0]; __syncthreads();
    float ev[4], sum = 0.0f;
#pragma unroll
    for (int j = 0; j < 4; j++) {
        ev[j] = __expf(e[j] - M) * mask[b * 1024 + tid + j * 256];
        sum += ev[j];
    }
    red[tid] = sum; __syncthreads();
    for (int s = 128; s > 0; s >>= 1) { if (tid < s) red[tid] += red[tid + s]; __syncthreads(); }
    float inv = __fdividef(1.0f, red[0]);
#pragma unroll
    for (int j = 0; j < 4; j++) {
        int i = b * 1024 + tid + j * 256;
        float a = ev[j] * inv;
        outp[O_A + i] = a;
        outp[O_COV + i] = coverage[i] + a;
    }
}

// =============== K7: c_t partials (streams enc_outs) — accumulates c_t directly ===============
__global__ void k_ctx(const float* __restrict__ enc_outs, const float* __restrict__ outp) {
    gdep_wait();
    gdep_launch();
    int chunk = blockIdx.x, b = blockIdx.y;
    __shared__ float sa[64];
    int tid = threadIdx.x;
    if (tid < 64) sa[tid] = outp[O_A + b * 1024 + chunk * 64 + tid];
    __syncthreads();
    const float2* p = (const float2*)(enc_outs + ((size_t)b * 1024 + chunk * 64) * 512);
    float2 acc = make_float2(0.0f, 0.0f);
#pragma unroll 8
    for (int i = 0; i < 64; i++) {
        float2 v = p[i * 256 + tid];
        float a = sa[i];
        acc.x += a * v.x;
        acc.y += a * v.y;
    }
    // a is already normalized -> partials sum directly to c_t
    atomicAdd(&g_ctT[(2 * tid) * 128 + b], acc.x);
    atomicAdd(&g_ctT[(2 * tid + 1) * 128 + b], acc.y);
}

// =============== K8: c_t copy-out + p_gen (runs OFF critical path on s2) ===============
__global__ void k_finalize(const float* __restrict__ pgen_W, const float* __restrict__ pgen_b,
                           float* __restrict__ outp) {
    gdep_wait();
    gdep_launch();
    int b = blockIdx.x, tid = threadIdx.x;     // 512
    __shared__ float red[512];
    float ct = g_ctT[tid * 128 + b];
    outp[O_CT + b * 512 + tid] = ct;
    float p = pgen_W[tid] * ct;
    float z2 = (tid < 256) ? outp[O_H + b * 256 + tid] : outp[O_C + b * 256 + (tid - 256)];
    p += pgen_W[512 + tid] * z2;
    if (tid < 128) p += pgen_W[1024 + tid] * g_xT[tid * 128 + b];
    red[tid] = p; __syncthreads();
    for (int st = 256; st > 0; st >>= 1) { if (tid < st) red[tid] += red[tid + st]; __syncthreads(); }
    if (tid == 0) outp[O_PG + b] = fsig(red[0] + pgen_b[0]);
}

// =============== K10: pipelined logits GEMM on tensor cores (tile loop) ===============
// Logits are tiny (|logit| << 1): softmax needs no max-subtraction.
// Store exp(logit+bias) directly; emit per-row tile sums only.
// Grid LGRID=296 (2/SM); each block loops tiles (tile += LGRID), reusing staged A.
#define SA_STRIDE 132
#define SB_STRIDE 20
#define SB_WORDS  (128 * SB_STRIDE)
#define SMEM_LOGITS ((128 * SA_STRIDE + 2 * SB_WORDS) * 4 + 128 * 4 + 128 * 4 * 4)

__global__ void __launch_bounds__(256) k_logits_mma(const float* __restrict__ outW,
                                                    const float* __restrict__ outb) {
    extern __shared__ uint32_t smem_dyn[];
    uint32_t* sA = smem_dyn;
    uint32_t* sB = sA + 128 * SA_STRIDE;
    float* s_bias = (float*)(sB + 2 * SB_WORDS);
    float* s_red  = s_bias + 128;                 // [128][4]

    int tid = threadIdx.x;
    int lane = tid & 31, wid = tid >> 5;
    int wm = wid >> 2, wn = wid & 3;
    int g = lane >> 2, tg = lane & 3;

    const int tile0 = blockIdx.x;

    // ---- pre-wait: inputs only (first tile's bias + first B chunk) ----
    {
        int v00 = tile0 * 128;
        if (tid < 128) s_bias[tid] = (v00 + tid < V_) ? outb[v00 + tid] : 0.0f;
    }
    float4 pw[4];
#pragma unroll
    for (int r = 0; r < 4; r++) {
        int idx = r * 256 + tid;
        int v = tile0 * 128 + (idx >> 3), f = idx & 7;
        pw[r] = (v < V_) ? *(const float4*)&outW[(size_t)v * 256 + f * 4]
                         : make_float4(0.f, 0.f, 0.f, 0.f);
    }
    gdep_wait();
    gdep_launch();
    // ---- stage A once (tile-independent) ----
#pragma unroll 8
    for (int r = 0; r < 64; r++) {
        int idx = r * 256 + tid;
        int b = idx & 127, w = idx >> 7;
        float lo = g_hidT[(2 * w) * 128 + b];
        float hi = g_hidT[(2 * w + 1) * 128 + b];
        sA[b * SA_STRIDE + w] = pkbf2(lo, hi);
    }

    for (int tile = tile0; tile < NTILE; tile += LGRID) {
        const int v0 = tile * 128;
        if (tile != tile0) {
            __syncthreads();   // previous tile fully done (epilogue reads of s_bias/s_red)
            if (tid < 128) s_bias[tid] = (v0 + tid < V_) ? outb[v0 + tid] : 0.0f;
#pragma unroll
            for (int r = 0; r < 4; r++) {
                int idx = r * 256 + tid;
                int v = v0 + (idx >> 3), f = idx & 7;
                pw[r] = (v < V_) ? *(const float4*)&outW[(size_t)v * 256 + f * 4]
                                 : make_float4(0.f, 0.f, 0.f, 0.f);
            }
        }
#pragma unroll
        for (int r = 0; r < 4; r++) {
            int idx = r * 256 + tid;
            int v = idx >> 3, f = idx & 7;
            sB[v * SB_STRIDE + f * 2]     = pkbf2(pw[r].x, pw[r].y);
            sB[v * SB_STRIDE + f * 2 + 1] = pkbf2(pw[r].z, pw[r].w);
        }
        __syncthreads();

        float acc[4][4][4];
#pragma unroll
        for (int mt = 0; mt < 4; mt++)
#pragma unroll
            for (int nt = 0; nt < 4; nt++)
#pragma unroll
                for (int q = 0; q < 4; q++) acc[mt][nt][q] = 0.0f;

#pragma unroll 1
        for (int it = 0; it < 8; it++) {
            if (it < 7) {
                int k0n = (it + 1) * 32;
#pragma unroll
                for (int r = 0; r < 4; r++) {
                    int idx = r * 256 + tid;
                    int v = v0 + (idx >> 3), f = idx & 7;
                    pw[r] = (v < V_) ? *(const float4*)&outW[(size_t)v * 256 + k0n + f * 4]
                                     : make_float4(0.f, 0.f, 0.f, 0.f);
                }
            }
            const uint32_t* sBp = sB + (it & 1) * SB_WORDS;
            int aw = it * 16;
#pragma unroll
            for (int kk = 0; kk < 2; kk++) {
                int kw = kk * 8 + tg;
                uint32_t a[4][4];
#pragma unroll
                for (int mt = 0; mt < 4; mt++) {
                    int r0 = wm * 64 + mt * 16 + g;
                    a[mt][0] = sA[r0 * SA_STRIDE + aw + kw];
                    a[mt][1] = sA[(r0 + 8) * SA_STRIDE + aw + kw];
                    a[mt][2] = sA[r0 * SA_STRIDE + aw + kw + 4];
                    a[mt][3] = sA[(r0 + 8) * SA_STRIDE + aw + kw + 4];
                }
#pragma unroll
                for (int nt = 0; nt < 4; nt++) {
                    int n0 = wn * 32 + nt * 8 + g;
                    uint32_t b0 = sBp[n0 * SB_STRIDE + kw];
                    uint32_t b1 = sBp[n0 * SB_STRIDE + kw + 4];
#pragma unroll
                    for (int mt = 0; mt < 4; mt++) {
                        asm volatile(
                            "mma.sync.aligned.m16n8k16.row.col.f32.bf16.bf16.f32 "
                            "{%0,%1,%2,%3},{%4,%5,%6,%7},{%8,%9},{%0,%1,%2,%3};"
                            : "+f"(acc[mt][nt][0]), "+f"(acc[mt][nt][1]),
                              "+f"(acc[mt][nt][2]), "+f"(acc[mt][nt][3])
                            : "r"(a[mt][0]), "r"(a[mt][1]), "r"(a[mt][2]), "r"(a[mt][3]),
                              "r"(b0), "r"(b1));
                    }
                }
            }
            if (it < 7) {
                uint32_t* sBn = sB + ((it + 1) & 1) * SB_WORDS;
#pragma unroll
                for (int r = 0; r < 4; r++) {
                    int idx = r * 256 + tid;
                    int v = idx >> 3, f = idx & 7;
                    sBn[v * SB_STRIDE + f * 2]     = pkbf2(pw[r].x, pw[r].y);
                    sBn[v * SB_STRIDE + f * 2 + 1] = pkbf2(pw[r].z, pw[r].w);
                }
            }
            __syncthreads();
        }

        // ---- epilogue: exp(logit+bias) stored; per-row tile sums ----
        int cbase = wn * 32 + tg * 2;
        bool val[4];
#pragma unroll
        for (int nt = 0; nt < 4; nt++) val[nt] = (v0 + cbase + nt * 8) < V_;
#pragma unroll
        for (int mt = 0; mt < 4; mt++) {
#pragma unroll
            for (int h = 0; h < 2; h++) {
                int row = wm * 64 + mt * 16 + g + h * 8;
                float s = 0.0f;
#pragma unroll
                for (int nt = 0; nt < 4; nt++) {
                    if (val[nt]) {
                        float bv0 = s_bias[cbase + nt * 8];
                        float bv1 = s_bias[cbase + nt * 8 + 1];
                        float e0 = __expf(acc[mt][nt][2 * h]     + bv0);
                        float e1 = __expf(acc[mt][nt][2 * h + 1] + bv1);
                        *(float2*)&g_logits[(size_t)row * V_ + v0 + cbase + nt * 8] = make_float2(e0, e1);
                        s += e0 + e1;
                    }
                }
                s += __shfl_xor_sync(0xffffffffu, s, 1);
                s += __shfl_xor_sync(0xffffffffu, s, 2);
                if (tg == 0) s_red[row * 4 + wn] = s;
            }
        }
        __syncthreads();
        if (tid < 128) {
            float s = s_red[tid * 4 + 0] + s_red[tid * 4 + 1] + s_red[tid * 4 + 2] + s_red[tid * 4 + 3];
            g_tsum[tid * NTILE + tile] = s;
        }
    }
}

// =============== K12: final vocab dist (float4) — combine fused in-block ===============
__global__ void k_final_vocab(const float* __restrict__ extra_zeros, float* __restrict__ outp) {
    gdep_wait();
    gdep_launch();
    int b = blockIdx.y;
    int tid = threadIdx.x;
    __shared__ float red[256];
    __shared__ float sSc;
    float s = 0.0f;
    for (int i = tid; i < NTILE; i += 256) s += g_tsum[b * NTILE + i];
    red[tid] = s; __syncthreads();
    for (int st = 128; st > 0; st >>= 1) { if (tid < st) red[tid] += red[tid + st]; __syncthreads(); }
    if (tid == 0) sSc = __fdividef(outp[O_PG + b], red[0]);
    __syncthreads();
    float sc = sSc;
    int q = blockIdx.x * 256 + tid;
    if (q < 12500) {
        float4 lg = *(const float4*)&g_logits[(size_t)b * V_ + q * 4];
        float4 o;
        o.x = sc * lg.x;
        o.y = sc * lg.y;
        o.z = sc * lg.z;
        o.w = sc * lg.w;
        *(float4*)&outp[O_FD + (size_t)b * VX_ + q * 4] = o;
    } else if (q < 12525) {
        int v = q * 4 - V_;
        float4 z = *(const float4*)&extra_zeros[b * X_ + v];
        *(float4*)&outp[O_FD + (size_t)b * VX_ + q * 4] = z;
    }
}

// =============== K13: pointer scatter-add ===============
__global__ void k_scatter(const int* __restrict__ ext_vocab, float* __restrict__ outp) {
    gdep_wait();
    gdep_launch();
    int i = blockIdx.x * 256 + threadIdx.x;
    int b = i >> 10;
    float pg = outp[O_PG + b];
    float av = outp[O_A + i];
    atomicAdd(&outp[O_FD + b * VX_ + ext_vocab[i]], (1.0f - pg) * av);
}

// ---------------- PDL launch helper (main stream) ----------------
template <typename... Args>
static inline void pdl_launch(dim3 g, dim3 b, size_t shm,
                              void (*f)(Args...), Args... a) {
    cudaLaunchConfig_t cfg = {};
    cfg.gridDim = g; cfg.blockDim = b; cfg.dynamicSmemBytes = shm; cfg.stream = 0;
    cudaLaunchAttribute at[1];
    at[0].id = cudaLaunchAttributeProgrammaticStreamSerialization;
    at[0].val.programmaticStreamSerializationAllowed = 1;
    cfg.attrs = at; cfg.numAttrs = 1;
    cudaLaunchKernelEx(&cfg, f, a...);
}

// ======================================================================
extern "C" void kernel_launch(void* const* d_in, const int* in_sizes, int n_in,
                              void* d_out, int out_size) {
    (void)in_sizes; (void)n_in; (void)out_size;
    const int*   y_t       = (const int*)d_in[0];
    const float* h0        = (const float*)d_in[1];
    const float* c0        = (const float*)d_in[2];
    const float* enc_outs  = (const float*)d_in[3];
    const float* enc_feats = (const float*)d_in[4];
    const float* mask      = (const float*)d_in[5];
    const float* c_t_1     = (const float*)d_in[6];
    const float* extra_z   = (const float*)d_in[7];
    const int*   ext_vocab = (const int*)d_in[8];
    const float* coverage  = (const float*)d_in[9];
    const float* embed_W   = (const float*)d_in[10];
    const float* Wih       = (const float*)d_in[11];
    const float* Whh       = (const float*)d_in[12];
    const float* bih       = (const float*)d_in[13];
    const float* bhh       = (const float*)d_in[14];
    const float* xctx_W    = (const float*)d_in[15];
    const float* xctx_b    = (const float*)d_in[16];
    const float* Ws_W      = (const float*)d_in[17];
    const float* Ws_b      = (const float*)d_in[18];
    const float* Wc_W      = (const float*)d_in[19];
    const float* v_W       = (const float*)d_in[20];
    const float* pgen_W    = (const float*)d_in[21];
    const float* pgen_b    = (const float*)d_in[22];
    const float* proj_W    = (const float*)d_in[23];
    const float* proj_b    = (const float*)d_in[24];
    const float* out_W     = (const float*)d_in[25];
    const float* out_b     = (const float*)d_in[26];
    float* outp = (float*)d_out;

    float* d_xT;     cudaGetSymbolAddress((void**)&d_xT, g_xT);
    float* d_gatesT; cudaGetSymbolAddress((void**)&d_gatesT, g_gatesT);
    float* d_hcT;    cudaGetSymbolAddress((void**)&d_hcT, g_hcT);
    float* d_decT;   cudaGetSymbolAddress((void**)&d_decT, g_decT);
    float* d_ctT;    cudaGetSymbolAddress((void**)&d_ctT, g_ctT);
    float* d_hidT;   cudaGetSymbolAddress((void**)&d_hidT, g_hidT);
    float* d_prepT;  cudaGetSymbolAddress((void**)&d_prepT, g_prepT);
    float* d_h0T;    cudaGetSymbolAddress((void**)&d_h0T, g_h0T);
    const float* cnull = nullptr;

    cudaFuncSetAttribute(k_logits_mma, cudaFuncAttributeMaxDynamicSharedMemorySize, SMEM_LOGITS);

    // side stream + events for fork-join capture (host handles only; no device mem)
    cudaStream_t s2;
    cudaStreamCreateWithFlags(&s2, cudaStreamNonBlocking);
    cudaEvent_t ev0, evG, ev1, ev2, evC, evF;
    cudaEventCreateWithFlags(&ev0, cudaEventDisableTiming);
    cudaEventCreateWithFlags(&evG, cudaEventDisableTiming);
    cudaEventCreateWithFlags(&ev1, cudaEventDisableTiming);
    cudaEventCreateWithFlags(&ev2, cudaEventDisableTiming);
    cudaEventCreateWithFlags(&evC, cudaEventDisableTiming);
    cudaEventCreateWithFlags(&evF, cudaEventDisableTiming);

    k_prep_zero<<<512, 256>>>(y_t, c_t_1, embed_W, h0);

    // fork: gates h0-half (K=256, biases) on s2, overlapping the x GEMM on main
    cudaEventRecord(ev0, 0);
    cudaStreamWaitEvent(s2, ev0, 0);
    k_gemm<<<dim3(32, 4, 4), 256, 0, s2>>>(d_h0T, Whh, 256, 256,
                                           cnull, cnull, 0, bih, bhh, d_gatesT);
    cudaEventRecord(evG, s2);

    // x = [c_t_1, emb] @ xctx_W.T + xctx_b   (K=640 -> 10 chunks)
    pdl_launch(dim3(4, 4, 10), dim3(256), 0, k_gemm,
               (const float*)d_prepT, xctx_W, 640, 640,
               cnull, cnull, 0, xctx_b, cnull, (float*)d_xT);
    // gates x-half (K=128 -> 2 chunks, no bias — applied in h0-half)
    pdl_launch(dim3(32, 4, 2), dim3(256), 0, k_gemm,
               (const float*)d_xT, Wih, 128, 128,
               cnull, cnull, 0, cnull, cnull, (float*)d_gatesT);
    // join both gates halves before lstm
    cudaStreamWaitEvent(0, evG, 0);
    pdl_launch(dim3(512), dim3(64), 0, k_lstm, c0, outp);

    // fork: h-half of hid GEMM overlaps the attention phase
    cudaEventRecord(ev1, 0);
    cudaStreamWaitEvent(s2, ev1, 0);
    k_gemm<<<dim3(8, 4, 4), 256, 0, s2>>>(d_hcT, proj_W, 768, 256,
                                          cnull, cnull, 0, proj_b, cnull, d_hidT);
    cudaEventRecord(ev2, s2);

    // dec = [h,c]@Ws_W.T + Ws_b              (K=512 -> 8 chunks)
    pdl_launch(dim3(16, 4, 8), dim3(256), 0, k_gemm,
               (const float*)d_hcT, Ws_W, 512, 512,
               cnull, cnull, 0, Ws_b, cnull, (float*)d_decT);
    pdl_launch(dim3(B_ * L_ / 16), dim3(256), 0, k_energy,
               enc_feats, coverage, Wc_W, v_W);
    pdl_launch(dim3(B_), dim3(256), 0, k_softmax_a, mask, coverage, outp);
    pdl_launch(dim3(16, B_), dim3(256), 0, k_ctx, enc_outs, (const float*)outp);

    // fork: finalize (c_t copy-out + p_gen) on s2 — off the critical path
    cudaEventRecord(evC, 0);
    cudaStreamWaitEvent(s2, evC, 0);
    k_finalize<<<B_, 512, 0, s2>>>(pgen_W, pgen_b, outp);
    cudaEventRecord(evF, s2);

    // ct-half of hid GEMM (K=512 -> 8 chunks), no bias (added in h-half)
    pdl_launch(dim3(8, 4, 8), dim3(256), 0, k_gemm,
               (const float*)d_ctT, (const float*)(proj_W + 256), 768, 512,
               cnull, cnull, 0, cnull, cnull, (float*)d_hidT);
    // join: logits needs both hid halves
    cudaStreamWaitEvent(0, ev2, 0);
    pdl_launch(dim3(LGRID), dim3(256), (size_t)SMEM_LOGITS, k_logits_mma, out_W, out_b);
    // join: final_vocab needs p_gen from finalize (s2)
    cudaStreamWaitEvent(0, evF, 0);
    pdl_launch(dim3(49, B_), dim3(256), 0, k_final_vocab, extra_z, outp);
    pdl_launch(dim3(B_ * L_ / 256), dim3(256), 0, k_scatter, ext_vocab, outp);
}